// round 2
// baseline (speedup 1.0000x reference)
#include <cuda_runtime.h>
#include <cstdint>

#define NN 4096
#define CC 128
#define NELLD 9
#define NSPEC 10
#define NPB 4
#define NPERM (NN + NSPEC * NPB)
#define USTRIDE 3276  /* floats per (c,s): 729*4 (u3) + 81*4 (u2) + 9*4 (u1) */

// ---------------- device scratch (no runtime allocation allowed) ----------------
__device__ float g_u[CC * NSPEC * USTRIDE];   // ~16.8 MB: weighted basis per (c, spec)
__device__ float g_f[4 * CC * NN];            // ~8.4 MB: contraction output [o][c][n]
__device__ int   g_perm[NPERM];
__device__ int   g_bstart[NSPEC];
__device__ int   g_bcnt[NSPEC];

// ---------------- f32x2 helpers --------------------------------------------------
__device__ __forceinline__ void fma2(unsigned long long& d, unsigned long long a,
                                     unsigned long long b) {
    asm("fma.rn.f32x2 %0, %1, %2, %0;" : "+l"(d) : "l"(a), "l"(b));
}
__device__ __forceinline__ void mul2(unsigned long long& d, unsigned long long a,
                                     unsigned long long b) {
    asm("mul.rn.f32x2 %0, %1, %2;" : "=l"(d) : "l"(a), "l"(b));
}
__device__ __forceinline__ void dup2(unsigned long long& d, float s) {
    asm("mov.b64 %0, {%1, %1};" : "=l"(d) : "f"(s));
}
__device__ __forceinline__ void unpack2(float& lo, float& hi, unsigned long long v) {
    asm("mov.b64 {%0, %1}, %2;" : "=f"(lo), "=f"(hi) : "l"(v));
}
__device__ __forceinline__ void lds_v2u64(unsigned long long& a, unsigned long long& b,
                                          uint32_t addr) {
    asm("ld.shared.v2.b64 {%0, %1}, [%2];" : "=l"(a), "=l"(b) : "r"(addr));
}

// ---------------- kernel 1: bucket nodes by species (NPB-padded buckets) --------
__global__ void bucket_kernel(const int* __restrict__ spec) {
    __shared__ int cnt[NSPEC];
    __shared__ int cur[NSPEC];
    const int tid = threadIdx.x;
    if (tid < NSPEC) cnt[tid] = 0;
    __syncthreads();
    for (int i = tid; i < NN; i += blockDim.x) atomicAdd(&cnt[spec[i]], 1);
    __syncthreads();
    if (tid == 0) {
        int off = 0;
        for (int s = 0; s < NSPEC; ++s) {
            g_bstart[s] = off;
            g_bcnt[s]   = cnt[s];
            cur[s]      = off;
            off += ((cnt[s] + NPB - 1) / NPB) * NPB;
        }
    }
    __syncthreads();
    for (int i = tid; i < NPERM; i += blockDim.x) g_perm[i] = -1;
    __syncthreads();
    for (int i = tid; i < NN; i += blockDim.x) {
        const int s = spec[i];
        const int pos = atomicAdd(&cur[s], 1);
        g_perm[pos] = i;
    }
}

// ---------------- kernel 2: precontract U with per-(spec,channel) weights -------
// layout per (c,s) blob: [729][o4] u3 | [81][o4] u2 | [9][o4] u1, o = {0e, 1o_0, 1o_1, 1o_2}
__global__ void __launch_bounds__(128) precompute_kernel(
    const float* __restrict__ U3_0e, const float* __restrict__ U2_0e, const float* __restrict__ U1_0e,
    const float* __restrict__ W3_0e, const float* __restrict__ W2_0e, const float* __restrict__ W1_0e,
    const float* __restrict__ U3_1o, const float* __restrict__ U2_1o, const float* __restrict__ U1_1o,
    const float* __restrict__ W3_1o, const float* __restrict__ W2_1o, const float* __restrict__ W1_1o) {
    const int c = blockIdx.x, s = blockIdx.y;
    float w3a[4], w3b[4], w2a[2], w2b[2];
#pragma unroll
    for (int k = 0; k < 4; ++k) {
        w3a[k] = W3_0e[(s * 4 + k) * CC + c];
        w3b[k] = W3_1o[(s * 4 + k) * CC + c];
    }
#pragma unroll
    for (int k = 0; k < 2; ++k) {
        w2a[k] = W2_0e[(s * 2 + k) * CC + c];
        w2b[k] = W2_1o[(s * 2 + k) * CC + c];
    }
    const float w1a = W1_0e[s * CC + c];
    const float w1b = W1_1o[s * CC + c];

    float4* dst = reinterpret_cast<float4*>(g_u + (c * NSPEC + s) * USTRIDE);
    for (int idx = threadIdx.x; idx < 729; idx += blockDim.x) {
        float4 v;
        v.x = U3_0e[idx * 4 + 0] * w3a[0] + U3_0e[idx * 4 + 1] * w3a[1] +
              U3_0e[idx * 4 + 2] * w3a[2] + U3_0e[idx * 4 + 3] * w3a[3];
        v.y = U3_1o[idx * 4 + 0] * w3b[0] + U3_1o[idx * 4 + 1] * w3b[1] +
              U3_1o[idx * 4 + 2] * w3b[2] + U3_1o[idx * 4 + 3] * w3b[3];
        v.z = U3_1o[(729 + idx) * 4 + 0] * w3b[0] + U3_1o[(729 + idx) * 4 + 1] * w3b[1] +
              U3_1o[(729 + idx) * 4 + 2] * w3b[2] + U3_1o[(729 + idx) * 4 + 3] * w3b[3];
        v.w = U3_1o[(1458 + idx) * 4 + 0] * w3b[0] + U3_1o[(1458 + idx) * 4 + 1] * w3b[1] +
              U3_1o[(1458 + idx) * 4 + 2] * w3b[2] + U3_1o[(1458 + idx) * 4 + 3] * w3b[3];
        dst[idx] = v;
    }
    float4* dst2 = dst + 729;
    for (int idx = threadIdx.x; idx < 81; idx += blockDim.x) {
        float4 v;
        v.x = U2_0e[idx * 2 + 0] * w2a[0] + U2_0e[idx * 2 + 1] * w2a[1];
        v.y = U2_1o[idx * 2 + 0] * w2b[0] + U2_1o[idx * 2 + 1] * w2b[1];
        v.z = U2_1o[(81 + idx) * 2 + 0] * w2b[0] + U2_1o[(81 + idx) * 2 + 1] * w2b[1];
        v.w = U2_1o[(162 + idx) * 2 + 0] * w2b[0] + U2_1o[(162 + idx) * 2 + 1] * w2b[1];
        dst2[idx] = v;
    }
    float4* dst1 = dst + 810;
    for (int idx = threadIdx.x; idx < 9; idx += blockDim.x) {
        float4 v;
        v.x = U1_0e[idx] * w1a;
        v.y = U1_1o[idx] * w1b;
        v.z = U1_1o[9 + idx] * w1b;
        v.w = U1_1o[18 + idx] * w1b;
        dst1[idx] = v;
    }
}

// ---------------- kernel 3: fused cubic-form contraction (f32x2) ----------------
// block = (spec s, channel c); smem holds ū(s,c); each thread handles NPB nodes.
// Inner step: mul.f32x2 + 2x fma.f32x2 = 3 instrs / 8 flops per node.
__global__ void __launch_bounds__(128) contract_kernel(const float* __restrict__ x) {
    const int s = blockIdx.x;
    const int c = blockIdx.y;
    __shared__ __align__(16) float su[USTRIDE];
    __shared__ float xsh[128 * 37];  // scalar x copy, stride 37 -> conflict-free

    const float* src = g_u + (c * NSPEC + s) * USTRIDE;
    for (int i = threadIdx.x; i < USTRIDE / 4; i += 128)
        reinterpret_cast<float4*>(su)[i] = reinterpret_cast<const float4*>(src)[i];
    __syncthreads();

    const int cnt = g_bcnt[s];
    const int start = g_bstart[s];
    const int ngroups = (cnt + NPB - 1) / NPB;

    const uint32_t su_base = (uint32_t)__cvta_generic_to_shared(su);
    const uint32_t su2_base = su_base + 729 * 16;
    const uint32_t su1_base = su_base + 810 * 16;
    float* myx = &xsh[threadIdx.x * 37];

    for (int g = threadIdx.x; g < ngroups; g += 128) {
        int nodes[NPB];
        unsigned long long xr2[NPB][9];  // duplicated-packed (x,x)
#pragma unroll
        for (int j = 0; j < NPB; ++j) {
            const int n = g_perm[start + g * NPB + j];
            nodes[j] = n;
            const float* xp = x + (long)(n < 0 ? 0 : n) * (CC * NELLD) + c * NELLD;
#pragma unroll
            for (int i = 0; i < 9; ++i) {
                const float v = (n >= 0) ? xp[i] : 0.f;
                dup2(xr2[j][i], v);
                myx[j * 9 + i] = v;
            }
        }

        unsigned long long acc01[NPB], acc23[NPB];
#pragma unroll
        for (int j = 0; j < NPB; ++j) { acc01[j] = 0ull; acc23[j] = 0ull; }

#pragma unroll 1
        for (int p = 0; p < 9; ++p) {
            unsigned long long xp2[NPB];
#pragma unroll
            for (int j = 0; j < NPB; ++j) dup2(xp2[j], myx[j * 9 + p]);  // dynamic p

            unsigned long long b01, b23;
            lds_v2u64(b01, b23, su1_base + p * 16);
#pragma unroll
            for (int j = 0; j < NPB; ++j) {
                fma2(acc01[j], b01, xp2[j]);
                fma2(acc23[j], b23, xp2[j]);
            }

            const uint32_t u2p = su2_base + p * 9 * 16;
            const uint32_t u3p = su_base + p * 81 * 16;
#pragma unroll
            for (int q = 0; q < 9; ++q) {
                unsigned long long xpq2[NPB];
#pragma unroll
                for (int j = 0; j < NPB; ++j) mul2(xpq2[j], xp2[j], xr2[j][q]);

                unsigned long long c01, c23;
                lds_v2u64(c01, c23, u2p + q * 16);
#pragma unroll
                for (int j = 0; j < NPB; ++j) {
                    fma2(acc01[j], c01, xpq2[j]);
                    fma2(acc23[j], c23, xpq2[j]);
                }
#pragma unroll
                for (int i = 0; i < 9; ++i) {
                    unsigned long long d01, d23;
                    lds_v2u64(d01, d23, u3p + (q * 9 + i) * 16);
#pragma unroll
                    for (int j = 0; j < NPB; ++j) {
                        unsigned long long m2;
                        mul2(m2, xpq2[j], xr2[j][i]);
                        fma2(acc01[j], d01, m2);
                        fma2(acc23[j], d23, m2);
                    }
                }
            }
        }
#pragma unroll
        for (int j = 0; j < NPB; ++j) {
            if (nodes[j] >= 0) {
                float o0, o1, o2, o3;
                unpack2(o0, o1, acc01[j]);
                unpack2(o2, o3, acc23[j]);
                g_f[(0 * CC + c) * NN + nodes[j]] = o0;
                g_f[(1 * CC + c) * NN + nodes[j]] = o1;
                g_f[(2 * CC + c) * NN + nodes[j]] = o2;
                g_f[(3 * CC + c) * NN + nodes[j]] = o3;
            }
        }
    }
}

// ---------------- kernel 4: e3nn Linear (4 small GEMMs, 64x128 tiles) ------------
// y[n,m] = (sum_c f[z][c][n] * W[c][m]) * (1/sqrt(C))  (+ bias for z==0)
__global__ void __launch_bounds__(256) linear_kernel(
    const float* __restrict__ W0, const float* __restrict__ W1,
    const float* __restrict__ bias, float* __restrict__ out) {
    const int z = blockIdx.y;
    const int n0 = blockIdx.x * 64;
    const float* A = g_f + z * (CC * NN);      // [c][n]
    const float* B = (z == 0) ? W0 : W1;       // [c][m]
    __shared__ float As[16][64];
    __shared__ float Bs[16][128];
    const int tid = threadIdx.x;
    const int r = tid >> 4;           // 0..15 : node group (4 nodes)
    const int cix = tid & 15;         // 0..15 : m group (8 cols)
    const int lr = tid >> 4, lcv = (tid & 15) << 2;
    const int br = tid >> 5, bcv = (tid & 31) << 2;
    float acc[4][8] = {};
    for (int kc = 0; kc < CC; kc += 16) {
        *reinterpret_cast<float4*>(&As[lr][lcv]) =
            *reinterpret_cast<const float4*>(A + (kc + lr) * NN + n0 + lcv);
        *reinterpret_cast<float4*>(&Bs[br][bcv]) =
            *reinterpret_cast<const float4*>(B + (kc + br) * CC + bcv);
        *reinterpret_cast<float4*>(&Bs[br + 8][bcv]) =
            *reinterpret_cast<const float4*>(B + (kc + br + 8) * CC + bcv);
        __syncthreads();
#pragma unroll
        for (int k = 0; k < 16; ++k) {
            float a[4], b[8];
#pragma unroll
            for (int i = 0; i < 4; ++i) a[i] = As[k][r * 4 + i];
#pragma unroll
            for (int j = 0; j < 8; ++j) b[j] = Bs[k][cix * 8 + j];
#pragma unroll
            for (int i = 0; i < 4; ++i)
#pragma unroll
                for (int j = 0; j < 8; ++j) acc[i][j] += a[i] * b[j];
        }
        __syncthreads();
    }
    const float scale = 0.088388347648318447f;  // 1/sqrt(128)
#pragma unroll
    for (int i = 0; i < 4; ++i) {
        const int n = n0 + r * 4 + i;
#pragma unroll
        for (int j = 0; j < 8; ++j) {
            const int m = cix * 8 + j;
            const float v = acc[i][j] * scale;
            if (z == 0)
                out[n * 512 + m] = v + bias[m];
            else
                out[n * 512 + 128 + m * 3 + (z - 1)] = v;
        }
    }
}

// ---------------- launch ---------------------------------------------------------
extern "C" void kernel_launch(void* const* d_in, const int* in_sizes, int n_in,
                              void* d_out, int out_size) {
    const float* x     = (const float*)d_in[0];
    const int*   spec  = (const int*)d_in[1];
    const float* U3_0e = (const float*)d_in[2];
    const float* U2_0e = (const float*)d_in[3];
    const float* U1_0e = (const float*)d_in[4];
    const float* W3_0e = (const float*)d_in[5];
    const float* W2_0e = (const float*)d_in[6];
    const float* W1_0e = (const float*)d_in[7];
    const float* U3_1o = (const float*)d_in[8];
    const float* U2_1o = (const float*)d_in[9];
    const float* U1_1o = (const float*)d_in[10];
    const float* W3_1o = (const float*)d_in[11];
    const float* W2_1o = (const float*)d_in[12];
    const float* W1_1o = (const float*)d_in[13];
    const float* Wl0   = (const float*)d_in[14];
    const float* Wl1   = (const float*)d_in[15];
    const float* bias  = (const float*)d_in[16];
    float* out = (float*)d_out;

    bucket_kernel<<<1, 1024>>>(spec);
    precompute_kernel<<<dim3(CC, NSPEC), 128>>>(U3_0e, U2_0e, U1_0e, W3_0e, W2_0e, W1_0e,
                                                U3_1o, U2_1o, U1_1o, W3_1o, W2_1o, W1_1o);
    contract_kernel<<<dim3(NSPEC, CC), 128>>>(x);
    linear_kernel<<<dim3(NN / 64, 4), 256>>>(Wl0, Wl1, bias, out);
}

// round 3
// speedup vs baseline: 1.6452x; 1.6452x over previous
#include <cuda_runtime.h>
#include <cstdint>

#define NN 4096
#define CC 128
#define NELLD 9
#define NSPEC 10
#define NPB 4
#define NPERM (NN + NSPEC * NPB)
#define NS3 165   /* #monomials p<=q<=i over 9 */
#define NS2 45    /* #monomials p<=q */
#define USTRIDE 876  /* floats per (c,s): 165*4 + 45*4 + 9*4 */

// ---------------- device scratch (no runtime allocation allowed) ----------------
__device__ float g_u[CC * NSPEC * USTRIDE];   // ~4.5 MB: symmetric weighted basis per (c,s)
__device__ float g_f[4 * CC * NN];            // ~8.4 MB: contraction output [o][c][n]
__device__ float g_u3s[NS3 * 4 * 4];          // symmetrized U3 [slot][o][k3]
__device__ float g_u2s[NS2 * 4 * 2];          // symmetrized U2 [slot][o][k2]
__device__ float g_u1s[9 * 4];                // U1 [p][o]
__device__ int   g_perm[NPERM];
__device__ int   g_bstart[NSPEC];
__device__ int   g_bcnt[NSPEC];

// ---------------- kernel 1: bucket nodes by species (NPB-padded buckets) --------
__global__ void bucket_kernel(const int* __restrict__ spec) {
    __shared__ int cnt[NSPEC];
    __shared__ int cur[NSPEC];
    const int tid = threadIdx.x;
    if (tid < NSPEC) cnt[tid] = 0;
    __syncthreads();
    for (int i = tid; i < NN; i += blockDim.x) atomicAdd(&cnt[spec[i]], 1);
    __syncthreads();
    if (tid == 0) {
        int off = 0;
        for (int s = 0; s < NSPEC; ++s) {
            g_bstart[s] = off;
            g_bcnt[s]   = cnt[s];
            cur[s]      = off;
            off += ((cnt[s] + NPB - 1) / NPB) * NPB;
        }
    }
    __syncthreads();
    for (int i = tid; i < NPERM; i += blockDim.x) g_perm[i] = -1;
    __syncthreads();
    for (int i = tid; i < NN; i += blockDim.x) {
        const int s = spec[i];
        const int pos = atomicAdd(&cur[s], 1);
        g_perm[pos] = i;
    }
}

// ---------------- kernel 1b: symmetrize U3/U2 over index permutations -----------
// g_u3s[slot][o][k] = sum over DISTINCT permutations (a,b,c) of (p<=q<=i) of U3[o][a][b][c][k]
__global__ void sym_kernel(
    const float* __restrict__ U3_0e, const float* __restrict__ U3_1o,
    const float* __restrict__ U2_0e, const float* __restrict__ U2_1o,
    const float* __restrict__ U1_0e, const float* __restrict__ U1_1o) {
    const int tid = threadIdx.x;
    // --- u3: 165 slots ---
    for (int slot = tid; slot < NS3; slot += blockDim.x) {
        // decode slot -> (p<=q<=i)
        int t = slot, p = 0, q, i;
        for (p = 0; p < 9; ++p) { int m = 9 - p; int n = m * (m + 1) / 2; if (t < n) break; t -= n; }
        for (q = p; q < 9; ++q) { int n = 9 - q; if (t < n) break; t -= n; }
        i = q + t;
        // distinct permutations
        int pa[6], pb[6], pc[6], np;
        if (p == q && q == i) { np = 1; pa[0] = p; pb[0] = q; pc[0] = i; }
        else if (p == q) { np = 3; pa[0]=p;pb[0]=p;pc[0]=i; pa[1]=p;pb[1]=i;pc[1]=p; pa[2]=i;pb[2]=p;pc[2]=p; }
        else if (q == i) { np = 3; pa[0]=p;pb[0]=q;pc[0]=q; pa[1]=q;pb[1]=p;pc[1]=q; pa[2]=q;pb[2]=q;pc[2]=p; }
        else { np = 6;
            pa[0]=p;pb[0]=q;pc[0]=i; pa[1]=p;pb[1]=i;pc[1]=q;
            pa[2]=q;pb[2]=p;pc[2]=i; pa[3]=q;pb[3]=i;pc[3]=p;
            pa[4]=i;pb[4]=p;pc[4]=q; pa[5]=i;pb[5]=q;pc[5]=p; }
        for (int o = 0; o < 4; ++o) {
            for (int k = 0; k < 4; ++k) {
                float acc = 0.f;
                for (int e = 0; e < np; ++e) {
                    int base = (pa[e] * 81 + pb[e] * 9 + pc[e]) * 4 + k;
                    acc += (o == 0) ? U3_0e[base] : U3_1o[(o - 1) * 729 * 4 + base];
                }
                g_u3s[slot * 16 + o * 4 + k] = acc;
            }
        }
    }
    // --- u2: 45 slots ---
    for (int slot = tid; slot < NS2; slot += blockDim.x) {
        int t = slot, p, q;
        for (p = 0; p < 9; ++p) { int n = 9 - p; if (t < n) break; t -= n; }
        q = p + t;
        for (int o = 0; o < 4; ++o) {
            for (int k = 0; k < 2; ++k) {
                float acc;
                if (o == 0) {
                    acc = U2_0e[(p * 9 + q) * 2 + k];
                    if (p != q) acc += U2_0e[(q * 9 + p) * 2 + k];
                } else {
                    acc = U2_1o[((o - 1) * 81 + p * 9 + q) * 2 + k];
                    if (p != q) acc += U2_1o[((o - 1) * 81 + q * 9 + p) * 2 + k];
                }
                g_u2s[slot * 8 + o * 2 + k] = acc;
            }
        }
    }
    // --- u1: 9 slots ---
    for (int pp = tid; pp < 9; pp += blockDim.x) {
        g_u1s[pp * 4 + 0] = U1_0e[pp];
        g_u1s[pp * 4 + 1] = U1_1o[pp];
        g_u1s[pp * 4 + 2] = U1_1o[9 + pp];
        g_u1s[pp * 4 + 3] = U1_1o[18 + pp];
    }
}

// ---------------- kernel 2: precontract symmetric U with (spec,channel) weights --
// layout per (c,s) blob: [165][o4] u3 | [45][o4] u2 | [9][o4] u1
__global__ void __launch_bounds__(128) precompute_kernel(
    const float* __restrict__ W3_0e, const float* __restrict__ W2_0e, const float* __restrict__ W1_0e,
    const float* __restrict__ W3_1o, const float* __restrict__ W2_1o, const float* __restrict__ W1_1o) {
    const int c = blockIdx.x, s = blockIdx.y;
    float w3[4][4], w2[4][2], w1[4];
#pragma unroll
    for (int k = 0; k < 4; ++k) {
        w3[0][k] = W3_0e[(s * 4 + k) * CC + c];
        const float wb = W3_1o[(s * 4 + k) * CC + c];
        w3[1][k] = wb; w3[2][k] = wb; w3[3][k] = wb;
    }
#pragma unroll
    for (int k = 0; k < 2; ++k) {
        w2[0][k] = W2_0e[(s * 2 + k) * CC + c];
        const float wb = W2_1o[(s * 2 + k) * CC + c];
        w2[1][k] = wb; w2[2][k] = wb; w2[3][k] = wb;
    }
    w1[0] = W1_0e[s * CC + c];
    w1[1] = w1[2] = w1[3] = W1_1o[s * CC + c];

    float4* dst3 = reinterpret_cast<float4*>(g_u + (c * NSPEC + s) * USTRIDE);
    float4* dst2 = dst3 + NS3;
    float4* dst1 = dst2 + NS2;
    for (int slot = threadIdx.x; slot < NS3; slot += blockDim.x) {
        float v[4];
#pragma unroll
        for (int o = 0; o < 4; ++o) {
            v[o] = 0.f;
#pragma unroll
            for (int k = 0; k < 4; ++k) v[o] += g_u3s[slot * 16 + o * 4 + k] * w3[o][k];
        }
        dst3[slot] = make_float4(v[0], v[1], v[2], v[3]);
    }
    for (int slot = threadIdx.x; slot < NS2; slot += blockDim.x) {
        float v[4];
#pragma unroll
        for (int o = 0; o < 4; ++o) {
            v[o] = 0.f;
#pragma unroll
            for (int k = 0; k < 2; ++k) v[o] += g_u2s[slot * 8 + o * 2 + k] * w2[o][k];
        }
        dst2[slot] = make_float4(v[0], v[1], v[2], v[3]);
    }
    for (int pp = threadIdx.x; pp < 9; pp += blockDim.x) {
        dst1[pp] = make_float4(g_u1s[pp * 4 + 0] * w1[0], g_u1s[pp * 4 + 1] * w1[1],
                               g_u1s[pp * 4 + 2] * w1[2], g_u1s[pp * 4 + 3] * w1[3]);
    }
}

// ---------------- kernel 3: symmetric cubic-form contraction --------------------
// block = (spec s, channel c); smem holds 3.5 KB of symmetric basis; each thread
// handles NPB nodes; triangular loops fully unrolled -> x stays in registers.
__global__ void __launch_bounds__(128) contract_kernel(const float* __restrict__ x) {
    const int s = blockIdx.x;
    const int c = blockIdx.y;
    __shared__ __align__(16) float su[USTRIDE];

    const float* src = g_u + (c * NSPEC + s) * USTRIDE;
    for (int i = threadIdx.x; i < USTRIDE / 4; i += 128)
        reinterpret_cast<float4*>(su)[i] = reinterpret_cast<const float4*>(src)[i];
    __syncthreads();

    const int cnt = g_bcnt[s];
    const int start = g_bstart[s];
    const int ngroups = (cnt + NPB - 1) / NPB;

    const float4* u3 = reinterpret_cast<const float4*>(su);
    const float4* u2 = u3 + NS3;
    const float4* u1 = u2 + NS2;

    for (int g = threadIdx.x; g < ngroups; g += 128) {
        int nodes[NPB];
        float xr[NPB][9];
#pragma unroll
        for (int j = 0; j < NPB; ++j) {
            const int n = g_perm[start + g * NPB + j];
            nodes[j] = n;
            const float* xp = x + (long)(n < 0 ? 0 : n) * (CC * NELLD) + c * NELLD;
#pragma unroll
            for (int i = 0; i < 9; ++i) xr[j][i] = (n >= 0) ? xp[i] : 0.f;
        }

        float acc[NPB][4] = {};
        int s3 = 0, s2 = 0;
#pragma unroll
        for (int p = 0; p < 9; ++p) {
            const float4 v1 = u1[p];
#pragma unroll
            for (int j = 0; j < NPB; ++j) {
                acc[j][0] += v1.x * xr[j][p];
                acc[j][1] += v1.y * xr[j][p];
                acc[j][2] += v1.z * xr[j][p];
                acc[j][3] += v1.w * xr[j][p];
            }
#pragma unroll
            for (int q = p; q < 9; ++q) {
                float m2[NPB];
                const float4 v2 = u2[s2];
                ++s2;
#pragma unroll
                for (int j = 0; j < NPB; ++j) {
                    m2[j] = xr[j][p] * xr[j][q];
                    acc[j][0] += v2.x * m2[j];
                    acc[j][1] += v2.y * m2[j];
                    acc[j][2] += v2.z * m2[j];
                    acc[j][3] += v2.w * m2[j];
                }
#pragma unroll
                for (int i = q; i < 9; ++i) {
                    const float4 v3 = u3[s3];
                    ++s3;
#pragma unroll
                    for (int j = 0; j < NPB; ++j) {
                        const float m = m2[j] * xr[j][i];
                        acc[j][0] += v3.x * m;
                        acc[j][1] += v3.y * m;
                        acc[j][2] += v3.z * m;
                        acc[j][3] += v3.w * m;
                    }
                }
            }
        }
#pragma unroll
        for (int j = 0; j < NPB; ++j) {
            if (nodes[j] >= 0) {
#pragma unroll
                for (int o = 0; o < 4; ++o)
                    g_f[(o * CC + c) * NN + nodes[j]] = acc[j][o];
            }
        }
    }
}

// ---------------- kernel 4: e3nn Linear (4 small GEMMs, 128x128 tiles) -----------
// y[n,m] = (sum_c f[z][c][n] * W[c][m]) * (1/sqrt(C))  (+ bias for z==0)
__global__ void __launch_bounds__(256) linear_kernel(
    const float* __restrict__ W0, const float* __restrict__ W1,
    const float* __restrict__ bias, float* __restrict__ out) {
    const int z = blockIdx.y;
    const int n0 = blockIdx.x * 128;
    const float* A = g_f + z * (CC * NN);      // [c][n]
    const float* B = (z == 0) ? W0 : W1;       // [c][m]
    __shared__ float As[8][128];
    __shared__ float Bs[8][128];
    const int tid = threadIdx.x;
    const int r = tid >> 4, cix = tid & 15;
    const int lk = tid >> 5, lv = (tid & 31) << 2;
    float acc[8][8] = {};
    for (int kc = 0; kc < CC; kc += 8) {
        *reinterpret_cast<float4*>(&As[lk][lv]) =
            *reinterpret_cast<const float4*>(A + (kc + lk) * NN + n0 + lv);
        *reinterpret_cast<float4*>(&Bs[lk][lv]) =
            *reinterpret_cast<const float4*>(B + (kc + lk) * CC + lv);
        __syncthreads();
#pragma unroll
        for (int k = 0; k < 8; ++k) {
            float a[8], b[8];
#pragma unroll
            for (int i = 0; i < 4; ++i) {
                a[i] = As[k][r * 8 + i];
                a[4 + i] = As[k][r * 8 + 4 + i];
                b[i] = Bs[k][cix * 8 + i];
                b[4 + i] = Bs[k][cix * 8 + 4 + i];
            }
#pragma unroll
            for (int i = 0; i < 8; ++i)
#pragma unroll
                for (int j = 0; j < 8; ++j) acc[i][j] += a[i] * b[j];
        }
        __syncthreads();
    }
    const float scale = 0.088388347648318447f;  // 1/sqrt(128)
#pragma unroll
    for (int i = 0; i < 8; ++i) {
        const int n = n0 + r * 8 + i;
#pragma unroll
        for (int j = 0; j < 8; ++j) {
            const int m = cix * 8 + j;
            const float v = acc[i][j] * scale;
            if (z == 0)
                out[n * 512 + m] = v + bias[m];
            else
                out[n * 512 + 128 + m * 3 + (z - 1)] = v;
        }
    }
}

// ---------------- launch ---------------------------------------------------------
extern "C" void kernel_launch(void* const* d_in, const int* in_sizes, int n_in,
                              void* d_out, int out_size) {
    const float* x     = (const float*)d_in[0];
    const int*   spec  = (const int*)d_in[1];
    const float* U3_0e = (const float*)d_in[2];
    const float* U2_0e = (const float*)d_in[3];
    const float* U1_0e = (const float*)d_in[4];
    const float* W3_0e = (const float*)d_in[5];
    const float* W2_0e = (const float*)d_in[6];
    const float* W1_0e = (const float*)d_in[7];
    const float* U3_1o = (const float*)d_in[8];
    const float* U2_1o = (const float*)d_in[9];
    const float* U1_1o = (const float*)d_in[10];
    const float* W3_1o = (const float*)d_in[11];
    const float* W2_1o = (const float*)d_in[12];
    const float* W1_1o = (const float*)d_in[13];
    const float* Wl0   = (const float*)d_in[14];
    const float* Wl1   = (const float*)d_in[15];
    const float* bias  = (const float*)d_in[16];
    float* out = (float*)d_out;

    bucket_kernel<<<1, 1024>>>(spec);
    sym_kernel<<<1, 256>>>(U3_0e, U3_1o, U2_0e, U2_1o, U1_0e, U1_1o);
    precompute_kernel<<<dim3(CC, NSPEC), 128>>>(W3_0e, W2_0e, W1_0e, W3_1o, W2_1o, W1_1o);
    contract_kernel<<<dim3(NSPEC, CC), 128>>>(x);
    linear_kernel<<<dim3(NN / 128, 4), 256>>>(Wl0, Wl1, bias, out);
}